// round 8
// baseline (speedup 1.0000x reference)
#include <cuda_runtime.h>
#include <cuda_bf16.h>
#include <cstdint>
#include <math.h>

// Sqrtm Newton-Schulz on tensor cores via mma.sync bf16 (sm_80+ PTX; harness
// PTX target is plain sm_103, which rejects tcgen05).
// Chain (verified):
//   normA = sum(x); A = x/normA; Z0 = 1.5I - 0.5A
//   Y1 = A@Z0
//   3x: ZY = 0.5*Y - 0.5*(Z@Y); Y' = Y@ZY; Z' = ZY@Z
//   T = 0.5*Y - 0.5*(Y@Z); out = (T@Y)*sqrt(normA)
// Symmetric outputs => 6 of 8 128x64 tiles; tiles 2,3 mirror-transpose the
// lower-left half. fp32 = bf16 hi+lo; 3 MMAs: Ah@Bh + Ah@Bl + Al@Bh.
//
// R8: persistent CTAs (296 = 2/SM), cross-tile software pipelining (next
// tile's chunk0/1 cp.async issued before current epilogue), independent
// GEMM pairs fused into one launch.

#define DMAT 256
#define MSZ  65536
#define BATCH 256
#define NCTA 296                 // 2 per SM x 148 SMs

#define STAGE 49152              // Ah 16K | Al 16K | Bh 8K | Bl 8K
#define OFF_BH 32768
#define SMEM_TOTAL (2 * STAGE)   // 96 KB

__device__ __nv_bfloat16 g_hi[5][(size_t)BATCH * MSZ];
__device__ __nv_bfloat16 g_lo[5][(size_t)BATCH * MSZ];
__device__ float g_inv[BATCH];
__device__ float g_sqrt[BATCH];

__device__ __forceinline__ uint32_t smem_u32(const void* p) {
    uint32_t a;
    asm("{ .reg .u64 t; cvta.to.shared.u64 t, %1; cvt.u32.u64 %0, t; }" : "=r"(a) : "l"(p));
    return a;
}

#define LDSM4(r, a) \
    asm volatile("ldmatrix.sync.aligned.m8n8.x4.shared.b16 {%0,%1,%2,%3}, [%4];" \
        : "=r"((r)[0]), "=r"((r)[1]), "=r"((r)[2]), "=r"((r)[3]) : "r"(a))

#define MMA(d, a, bb) \
    asm volatile("mma.sync.aligned.m16n8k16.row.col.f32.bf16.bf16.f32 " \
        "{%0,%1,%2,%3}, {%4,%5,%6,%7}, {%8,%9}, {%0,%1,%2,%3};" \
        : "+f"((d)[0]), "+f"((d)[1]), "+f"((d)[2]), "+f"((d)[3]) \
        : "r"((a)[0]), "r"((a)[1]), "r"((a)[2]), "r"((a)[3]), \
          "r"((bb)[0]), "r"((bb)[1]))

// ---------------------------------------------------------------------------
__global__ void norm_kernel(const float* __restrict__ x) {
    const int b = blockIdx.x;
    const float* p = x + (size_t)b * MSZ;
    float s = 0.f;
    for (int i = threadIdx.x; i < MSZ; i += 256) s += p[i];
    __shared__ float sh[256];
    sh[threadIdx.x] = s;
    __syncthreads();
    for (int off = 128; off > 0; off >>= 1) {
        if (threadIdx.x < off) sh[threadIdx.x] += sh[threadIdx.x + off];
        __syncthreads();
    }
    if (threadIdx.x == 0) {
        float n = sh[0];
        g_inv[b] = 1.0f / n;
        g_sqrt[b] = sqrtf(n);
    }
}

__global__ void setup_kernel(const float* __restrict__ x) {
    const size_t idx = (size_t)blockIdx.x * blockDim.x + threadIdx.x;
    const int b = (int)(idx >> 16);
    const int ij = (int)(idx & (MSZ - 1));
    const float a = x[idx] * g_inv[b];
    const int i = ij >> 8, j = ij & 255;
    const float z = (i == j ? 1.5f : 0.0f) - 0.5f * a;

    __nv_bfloat16 ah = __float2bfloat16_rn(a);
    __nv_bfloat16 al = __float2bfloat16_rn(a - __bfloat162float(ah));
    __nv_bfloat16 zh = __float2bfloat16_rn(z);
    __nv_bfloat16 zl = __float2bfloat16_rn(z - __bfloat162float(zh));
    g_hi[0][idx] = ah;  g_lo[0][idx] = al;
    g_hi[3][idx] = zh;  g_lo[3][idx] = zl;
}

// ---------------------------------------------------------------------------
struct GPar {
    size_t mo;
    int ia, ib, iy, idst, mode, b, mBase, nBase;
    bool mir;
};

// Persistent batched GEMM. Work item -> (param set, tile 0..5, batch).
// Items [0, half) use set 0, [half, nItems) use set 1.
__global__ void __launch_bounds__(256, 2)
gemm_pers(int ia0, int ib0, int iy0, int id0, int mode0,
          int ia1, int ib1, int iy1, int id1, int mode1,
          int half, int nItems, float* __restrict__ outp)
{
    extern __shared__ __align__(128) char smem[];
    const uint32_t sbase = smem_u32(smem);
    const int tid = threadIdx.x, wid = tid >> 5, lane = tid & 31;

    auto resolve = [&](int it, GPar& P) {
        int ih = it;
        if (it < half) { P.ia = ia0; P.ib = ib0; P.iy = iy0; P.idst = id0; P.mode = mode0; }
        else { ih = it - half; P.ia = ia1; P.ib = ib1; P.iy = iy1; P.idst = id1; P.mode = mode1; }
        const int tile = ih % 6;
        P.b = ih / 6;
        P.mo = (size_t)P.b * MSZ;
        P.mBase = (tile >= 4) ? 128 : 0;
        P.nBase = (tile < 4) ? tile * 64 : (tile - 2) * 64;
        P.mir = (tile == 2) || (tile == 3);
    };

    auto load_chunk = [&](const GPar& P, int stage, int c) {
        const __nv_bfloat16* Ah = g_hi[P.ia] + P.mo;
        const __nv_bfloat16* Al = g_lo[P.ia] + P.mo;
        const __nv_bfloat16* Bh = g_hi[P.ib] + P.mo;
        const __nv_bfloat16* Bl = g_lo[P.ib] + P.mo;
        const uint32_t sb = sbase + stage * STAGE;
        const int kc = c * 64;
        #pragma unroll
        for (int it = 0; it < 12; ++it) {
            const int i = tid + it * 256;        // 0..3071
            int plane, row, gRow;
            uint32_t dstOff;
            if (i < 2048) {                      // A: 2 planes x 128 rows x 8
                plane = i >> 10;
                const int rem = i & 1023;
                row = rem >> 3;
                gRow = P.mBase + row;
                dstOff = plane * 16384u;
            } else {                             // B: 2 planes x 64 rows x 8
                const int j = i - 2048;
                plane = j >> 9;
                const int rem = j & 511;
                row = rem >> 3;
                gRow = P.nBase + row;
                dstOff = OFF_BH + plane * 8192u;
            }
            const int seg = i & 7;
            const __nv_bfloat16* sp =
                (i < 2048) ? (plane ? Al : Ah) : (plane ? Bl : Bh);
            const void* src = sp + (size_t)gRow * DMAT + kc + seg * 8;
            const uint32_t dst = sb + dstOff + row * 128 +
                                 ((seg ^ (row & 7)) * 16);
            asm volatile("cp.async.cg.shared.global [%0], [%1], 16;"
                         :: "r"(dst), "l"(src));
        }
        asm volatile("cp.async.commit_group;" ::: "memory");
    };

    const int warpM = wid & 3;   // 4 warps over M (32 rows each)
    const int warpN = wid >> 2;  // 2 warps over N (32 cols each)
    const int r16 = lane & 15, chf = lane >> 4, xr = lane & 7;
    const uint32_t aRow0 = (uint32_t)(warpM * 32 + r16) * 128;
    const uint32_t bRow0 = OFF_BH + (uint32_t)(warpN * 32 + r16) * 128;
    const int r4 = lane >> 2, c2 = (lane & 3) * 2;
    uint32_t* sm32 = (uint32_t*)(smem + STAGE);   // mirror staging in stage 1

    int item = blockIdx.x;
    if (item >= nItems) return;
    GPar P;
    resolve(item, P);
    load_chunk(P, 0, 0);
    load_chunk(P, 1, 1);

    for (;;) {
        float acc[2][4][4] = {};

        #pragma unroll 1
        for (int c = 0; c < 4; ++c) {
            if (c < 3) asm volatile("cp.async.wait_group 1;" ::: "memory");
            else       asm volatile("cp.async.wait_group 0;" ::: "memory");
            __syncthreads();
            {   // compute chunk in stage c&1
                const uint32_t sb = sbase + (uint32_t)((c & 1) * STAGE);
                #pragma unroll
                for (int ks = 0; ks < 4; ++ks) {
                    const uint32_t sw = (uint32_t)(((ks * 2 + chf) ^ xr) * 16);
                    uint32_t ahf[2][4], alf[2][4], bhf[4][2], blf[4][2];
                    #pragma unroll
                    for (int mt = 0; mt < 2; ++mt) {
                        const uint32_t addr = sb + aRow0 + (uint32_t)(mt * 2048) + sw;
                        LDSM4(ahf[mt], addr);
                        LDSM4(alf[mt], addr + 16384);
                    }
                    #pragma unroll
                    for (int np = 0; np < 2; ++np) {
                        const uint32_t addr = sb + bRow0 + (uint32_t)(np * 2048) + sw;
                        uint32_t t[4];
                        LDSM4(t, addr);
                        bhf[np * 2][0] = t[0];      bhf[np * 2][1] = t[2];
                        bhf[np * 2 + 1][0] = t[1];  bhf[np * 2 + 1][1] = t[3];
                        LDSM4(t, addr + 8192);
                        blf[np * 2][0] = t[0];      blf[np * 2][1] = t[2];
                        blf[np * 2 + 1][0] = t[1];  blf[np * 2 + 1][1] = t[3];
                    }
                    #pragma unroll
                    for (int mt = 0; mt < 2; ++mt)
                        #pragma unroll
                        for (int nt = 0; nt < 4; ++nt)
                            MMA(acc[mt][nt], ahf[mt], bhf[nt]);
                    #pragma unroll
                    for (int mt = 0; mt < 2; ++mt)
                        #pragma unroll
                        for (int nt = 0; nt < 4; ++nt)
                            MMA(acc[mt][nt], ahf[mt], blf[nt]);
                    #pragma unroll
                    for (int mt = 0; mt < 2; ++mt)
                        #pragma unroll
                        for (int nt = 0; nt < 4; ++nt)
                            MMA(acc[mt][nt], alf[mt], bhf[nt]);
                }
            }
            __syncthreads();
            if (c < 2) load_chunk(P, c & 1, c + 2);
        }

        // ---- prefetch next item's first chunks before epilogue ----
        const int nextItem = item + NCTA;
        const bool hasNext = nextItem < nItems;
        GPar Pn;
        if (hasNext) {
            resolve(nextItem, Pn);
            load_chunk(Pn, 0, 0);                 // stage 0 is free
            if (!P.mir) load_chunk(Pn, 1, 1);     // stage 1 free unless mirror
        }

        // ---- epilogue ----
        const float sc = g_sqrt[P.b];
        const __nv_bfloat16* Yh = g_hi[P.iy] + P.mo;
        const __nv_bfloat16* Yl = g_lo[P.iy] + P.mo;
        __nv_bfloat16* Dh = g_hi[P.idst] + P.mo;
        __nv_bfloat16* Dl = g_lo[P.idst] + P.mo;
        float* Of = outp + P.mo;

        #pragma unroll
        for (int mt = 0; mt < 2; ++mt)
            #pragma unroll
            for (int nt = 0; nt < 4; ++nt)
                #pragma unroll
                for (int h = 0; h < 2; ++h) {
                    const int rloc = warpM * 32 + mt * 16 + r4 + h * 8;
                    const int cloc = warpN * 32 + nt * 8 + c2;
                    const int row = P.mBase + rloc, col = P.nBase + cloc;
                    float v0 = acc[mt][nt][h * 2];
                    float v1 = acc[mt][nt][h * 2 + 1];
                    const size_t off = (size_t)row * DMAT + col;
                    if (P.mode == 1) {
                        const uint32_t hw = *(const uint32_t*)(Yh + off);
                        const uint32_t lw = *(const uint32_t*)(Yl + off);
                        const float y0 = __uint_as_float(hw << 16) +
                                         __uint_as_float(lw << 16);
                        const float y1 = __uint_as_float(hw & 0xffff0000u) +
                                         __uint_as_float(lw & 0xffff0000u);
                        v0 = 0.5f * y0 - 0.5f * v0;
                        v1 = 0.5f * y1 - 0.5f * v1;
                    }
                    if (P.mode == 2) {
                        v0 *= sc;  v1 *= sc;
                        *(float2*)(Of + off) = make_float2(v0, v1);
                        if (P.mir) {
                            sm32[rloc * 65 + cloc]     = __float_as_uint(v0);
                            sm32[rloc * 65 + cloc + 1] = __float_as_uint(v1);
                        }
                    } else {
                        const __nv_bfloat16 h0 = __float2bfloat16_rn(v0);
                        const __nv_bfloat16 h1 = __float2bfloat16_rn(v1);
                        const __nv_bfloat16 l0 =
                            __float2bfloat16_rn(v0 - __bfloat162float(h0));
                        const __nv_bfloat16 l1 =
                            __float2bfloat16_rn(v1 - __bfloat162float(h1));
                        __nv_bfloat162 hp = __halves2bfloat162(h0, h1);
                        __nv_bfloat162 lp = __halves2bfloat162(l0, l1);
                        const uint32_t hpw = *(uint32_t*)&hp;
                        const uint32_t lpw = *(uint32_t*)&lp;
                        *(uint32_t*)(Dh + off) = hpw;
                        *(uint32_t*)(Dl + off) = lpw;
                        if (P.mir) {
                            sm32[rloc * 65 + cloc] =
                                (hpw & 0xffffu) | (lpw << 16);
                            sm32[rloc * 65 + cloc + 1] =
                                (hpw >> 16) | (lpw & 0xffff0000u);
                        }
                    }
                }

        if (P.mir) {
            __syncthreads();
            const int mrBase = 128 + ((P.nBase >> 6) - 2) * 64;
            #pragma unroll
            for (int it = 0; it < 16; ++it) {
                const int e = tid + it * 256;         // 0..4095 (pairs)
                const int i = e >> 6;                 // mirror row 0..63
                const int j = (e & 63) * 2;           // mirror col, even
                const uint32_t w0 = sm32[j * 65 + i];
                const uint32_t w1 = sm32[(j + 1) * 65 + i];
                const size_t off = (size_t)(mrBase + i) * DMAT + j;
                if (P.mode == 2) {
                    *(float2*)(Of + off) =
                        make_float2(__uint_as_float(w0), __uint_as_float(w1));
                } else {
                    *(uint32_t*)(Dh + off) = (w0 & 0xffffu) | (w1 << 16);
                    *(uint32_t*)(Dl + off) = (w0 >> 16) | (w1 & 0xffff0000u);
                }
            }
            __syncthreads();
            if (hasNext) load_chunk(Pn, 1, 1);   // stage 1 now free
        }

        if (!hasNext) break;
        P = Pn;
        item = nextItem;
    }
}

// ---------------------------------------------------------------------------
extern "C" void kernel_launch(void* const* d_in, const int* in_sizes, int n_in,
                              void* d_out, int out_size) {
    const float* x = (const float*)d_in[0];
    float* out = (float*)d_out;
    (void)in_sizes; (void)n_in; (void)out_size;

    cudaFuncSetAttribute(gemm_pers, cudaFuncAttributeMaxDynamicSharedMemorySize,
                         SMEM_TOTAL);

    norm_kernel<<<BATCH, 256>>>(x);
    setup_kernel<<<(BATCH * MSZ) / 256, 256>>>(x);

    const int ONE = 6 * BATCH;        // 1536
    #define G1(ia, ib, iy, idst, mode) \
        gemm_pers<<<NCTA, 256, SMEM_TOTAL>>>(ia, ib, iy, idst, mode, \
                                             ia, ib, iy, idst, mode, \
                                             ONE, ONE, out)
    #define G2(ia0, ib0, id0, ia1, ib1, id1) \
        gemm_pers<<<NCTA, 256, SMEM_TOTAL>>>(ia0, ib0, 0, id0, 0, \
                                             ia1, ib1, 0, id1, 0, \
                                             ONE, 2 * ONE, out)

    G1(0, 3, 0, 1, 0);        // Y1(1) = A(0)@Z0(3)
    // iter 1
    G1(3, 1, 1, 2, 1);        // ZY(2) = 0.5*Y(1) - 0.5*Z(3)@Y(1)
    G2(1, 2, 0,  2, 3, 4);    // Y2(0) = Y(1)@ZY(2) ; Z2(4) = ZY(2)@Z(3)
    // iter 2
    G1(4, 0, 0, 2, 1);        // ZY(2) = 0.5*Y(0) - 0.5*Z(4)@Y(0)
    G2(0, 2, 1,  2, 4, 3);    // Y3(1) = Y(0)@ZY(2) ; Z3(3) = ZY(2)@Z(4)
    // iter 3
    G1(3, 1, 1, 2, 1);        // ZY(2) = 0.5*Y(1) - 0.5*Z(3)@Y(1)
    G2(1, 2, 0,  2, 3, 4);    // Y4(0) = Y(1)@ZY(2) ; Z4(4) = ZY(2)@Z(3)
    // final
    G1(0, 4, 0, 2, 1);        // T(2) = 0.5*Y(0) - 0.5*Y(0)@Z(4)
    G1(2, 0, 0, 0, 2);        // out = T(2)@Y(0) * sqrt(normA)
    #undef G1
    #undef G2
}